// round 13
// baseline (speedup 1.0000x reference)
#include <cuda_runtime.h>
#include <cuda_fp16.h>
#include <cstdint>

#define N_TOK  12288
#define TILE_M 128
#define TILE_N 64
#define NIT    96          // i-tiles
#define NJT    192         // j-tiles
#define NSPLIT 3
#define TPC    64          // j-tiles per CTA
#define PSCALE 0.7f
#define NTHREADS 768       // 16 consumer warps + 8 producer warps

#define PSTR_P 72          // halves per P row (144 B)
#define PSTR_V 136         // halves per V row (272 B)
#define PB     18432       // P buffer bytes (128*144)
#define VB     17408       // V buffer bytes (64*272)
#define AB     32768       // adj buffer bytes (128*64*4)

// smem byte offsets
#define SM_P    0              // 2 buffers
#define SM_V    36864          // 2 buffers
#define SM_ADJ  71680          // 2 buffers
#define SM_RS   137216         // 128 floats
#define SMEM_TOTAL 137728

// ---------------- scratch (static device globals) ----------------
__device__ __half g_xt[(size_t)N_TOK * 128];
__device__ float  g_e1[N_TOK];
__device__ float  g_e1p[N_TOK];
__device__ float  g_e2[N_TOK];
__device__ float  g_e2p[N_TOK];
__device__ float  g_pc[(size_t)NSPLIT * N_TOK * 128];   // partial C
__device__ float  g_prs[(size_t)NSPLIT * N_TOK];        // partial rowsums

// ---------------- PTX helpers ----------------
__device__ __forceinline__ uint32_t smem_u32(const void* p) {
    return (uint32_t)__cvta_generic_to_shared(p);
}
__device__ __forceinline__ void cp16(uint32_t dst, const void* src) {
    asm volatile("cp.async.cg.shared.global [%0], [%1], 16;" :: "r"(dst), "l"(src));
}
#define CP_COMMIT() asm volatile("cp.async.commit_group;" ::: "memory")
#define CP_WAIT(n)  asm volatile("cp.async.wait_group %0;" :: "n"(n) : "memory")
#define BAR_SYNC(id)   asm volatile("bar.sync %0, %1;" :: "r"(id), "n"(NTHREADS) : "memory")
#define BAR_ARRIVE(id) asm volatile("bar.arrive %0, %1;" :: "r"(id), "n"(NTHREADS) : "memory")
__device__ __forceinline__ void ldsm_x4(uint32_t addr, uint32_t& r0, uint32_t& r1,
                                        uint32_t& r2, uint32_t& r3) {
    asm volatile("ldmatrix.sync.aligned.m8n8.x4.shared.b16 {%0,%1,%2,%3}, [%4];"
                 : "=r"(r0), "=r"(r1), "=r"(r2), "=r"(r3) : "r"(addr));
}
__device__ __forceinline__ void ldsm_x4_t(uint32_t addr, uint32_t& r0, uint32_t& r1,
                                          uint32_t& r2, uint32_t& r3) {
    asm volatile("ldmatrix.sync.aligned.m8n8.x4.trans.shared.b16 {%0,%1,%2,%3}, [%4];"
                 : "=r"(r0), "=r"(r1), "=r"(r2), "=r"(r3) : "r"(addr));
}
__device__ __forceinline__ void mma16816(float* c, const uint32_t* a, const uint32_t* b) {
    asm volatile("mma.sync.aligned.m16n8k16.row.col.f32.f16.f16.f32 "
                 "{%0,%1,%2,%3}, {%4,%5,%6,%7}, {%8,%9}, {%0,%1,%2,%3};"
                 : "+f"(c[0]), "+f"(c[1]), "+f"(c[2]), "+f"(c[3])
                 : "r"(a[0]), "r"(a[1]), "r"(a[2]), "r"(a[3]), "r"(b[0]), "r"(b[1]));
}

// ---------------- prep ----------------
__global__ __launch_bounds__(256) void prep_kernel(const float* __restrict__ x,
                                                   const float* __restrict__ a) {
    int gw   = (blockIdx.x * blockDim.x + threadIdx.x) >> 5;
    int lane = threadIdx.x & 31;
    if (gw >= N_TOK) return;

    const float4 xv = ((const float4*)(x + (size_t)gw * 128))[lane];
    float ss = xv.x * xv.x + xv.y * xv.y + xv.z * xv.z + xv.w * xv.w;
    #pragma unroll
    for (int o = 16; o; o >>= 1) ss += __shfl_xor_sync(0xffffffffu, ss, o);

    float norm = sqrtf(ss);
    float n    = fminf(fmaxf(norm, 1e-7f), 1.0f - 1e-7f);
    float fac  = atanhf(n) / n;
    float t0 = xv.x * fac, t1 = xv.y * fac, t2 = xv.z * fac, t3 = xv.w * fac;

    const float4 a1 = ((const float4*)a)[lane];
    const float4 a2 = ((const float4*)(a + 128))[lane];
    float w1 = t0 * a1.x + t1 * a1.y + t2 * a1.z + t3 * a1.w;
    float w2 = t0 * a2.x + t1 * a2.y + t2 * a2.z + t3 * a2.w;
    #pragma unroll
    for (int o = 16; o; o >>= 1) {
        w1 += __shfl_xor_sync(0xffffffffu, w1, o);
        w2 += __shfl_xor_sync(0xffffffffu, w2, o);
    }

    __half2* dst = (__half2*)(g_xt + (size_t)gw * 128);
    dst[lane * 2]     = __floats2half2_rn(t0, t1);
    dst[lane * 2 + 1] = __floats2half2_rn(t2, t3);

    if (lane == 0) {
        g_e1 [gw] = PSCALE * __expf(w1);
        g_e1p[gw] = PSCALE * __expf(0.2f * w1);
        g_e2 [gw] = __expf(w2);
        g_e2p[gw] = __expf(0.2f * w2);
    }
}

// ---------------- attention partial: warp-specialized producer/consumer ----------------
__global__ __launch_bounds__(NTHREADS, 1) void attn_kernel(const int* __restrict__ adj) {
    extern __shared__ char smem[];
    float* rs = (float*)(smem + SM_RS);

    const int tid = threadIdx.x;
    const int s   = blockIdx.x / NIT;
    const int it  = blockIdx.x % NIT;
    const int i0  = it * TILE_M;
    const int jtb = s * TPC;

    const int lane = tid & 31, wid = tid >> 5;
    const uint32_t smb = smem_u32(smem);

    if (tid < TILE_M) rs[tid] = 0.f;
    __syncthreads();

    if (wid >= 16) {
        // ================= PRODUCER (warps 16-23, 256 threads) =================
        const int ptid = tid - 512;
        const int il = ptid >> 1, jq = ptid & 1;       // row il, 32-col half jq
        const float e1  = g_e1 [i0 + il];
        const float e1p = g_e1p[i0 + il];
        const int* arowp = adj + (size_t)(i0 + il) * N_TOK + jq * 32;

        auto adj_cp = [&](int jt, int b) {             // self-owned 128 B
            const int* src = arowp + jt * TILE_N;
            uint32_t dst = smb + SM_ADJ + b * AB + ptid * 128;
            #pragma unroll
            for (int q = 0; q < 8; ++q) cp16(dst + q * 16, src + q * 4);
        };
        auto v_cp = [&](int jt, int b) {
            const __half* src = g_xt + (size_t)jt * TILE_N * 128;
            #pragma unroll
            for (int q = 0; q < 4; ++q) {
                int idx = q * 256 + ptid;
                int r = idx >> 4, ch = idx & 15;
                cp16(smb + SM_V + b * VB + r * (PSTR_V * 2) + ch * 16,
                     src + (size_t)r * 128 + ch * 8);
            }
        };
        auto pgen = [&](int jt, int b) {
            const int j0 = jt * TILE_N;
            const float4* e2v  = (const float4*)(g_e2  + j0 + jq * 32);
            const float4* e2pv = (const float4*)(g_e2p + j0 + jq * 32);
            const char* abase = smem + SM_ADJ + b * AB + ptid * 128;
            union { __half h[32]; uint4 u4[8]; } pk;
            float psum = 0.f;
            #pragma unroll
            for (int q = 0; q < 8; ++q) {
                uint4 av = *(const uint4*)(abase + q * 16);
                float4 ev  = __ldg(e2v + q);
                float4 epv = __ldg(e2pv + q);
                float p0 = fmaxf(e1 * ev.x, e1p * epv.x);
                float p1 = fmaxf(e1 * ev.y, e1p * epv.y);
                float p2 = fmaxf(e1 * ev.z, e1p * epv.z);
                float p3 = fmaxf(e1 * ev.w, e1p * epv.w);
                p0 = av.x ? p0 : 0.f;  p1 = av.y ? p1 : 0.f;
                p2 = av.z ? p2 : 0.f;  p3 = av.w ? p3 : 0.f;
                psum += (p0 + p1) + (p2 + p3);
                pk.h[q * 4 + 0] = __float2half_rn(p0);
                pk.h[q * 4 + 1] = __float2half_rn(p1);
                pk.h[q * 4 + 2] = __float2half_rn(p2);
                pk.h[q * 4 + 3] = __float2half_rn(p3);
            }
            uint4* pd = (uint4*)(smem + SM_P + b * PB + il * (PSTR_P * 2) + jq * 64);
            #pragma unroll
            for (int q = 0; q < 4; ++q) pd[q] = pk.u4[q];
            psum += __shfl_xor_sync(0xffffffffu, psum, 1);
            if (jq == 0) rs[il] += psum;
        };

        adj_cp(jtb, 0); CP_COMMIT();                   // adj(0) in flight

        #pragma unroll 1
        for (int t = 0; t < TPC; ++t) {
            const int b = t & 1;
            if (t >= 2) BAR_SYNC(3 + b);               // empty[b]: MMA(t-2) done
            v_cp(jtb + t, b); CP_COMMIT();
            if (t + 1 < TPC) {
                adj_cp(jtb + t + 1, b ^ 1); CP_COMMIT();
                CP_WAIT(2);                            // adj(t) arrived
            } else {
                CP_WAIT(1);                            // adj(t) arrived
            }
            pgen(jtb + t, b);
            if (t + 1 < TPC) CP_WAIT(1);               // V(t) arrived (adj(t+1) flying)
            else             CP_WAIT(0);
            BAR_ARRIVE(1 + b);                         // full[b]
        }
    } else {
        // ================= CONSUMER (warps 0-15, 512 threads) =================
        const int wm = wid & 3, wn = wid >> 2;
        float acc[2][4][4];
        #pragma unroll
        for (int mt = 0; mt < 2; ++mt)
            #pragma unroll
            for (int nt = 0; nt < 4; ++nt)
                #pragma unroll
                for (int e = 0; e < 4; ++e) acc[mt][nt][e] = 0.f;

        #pragma unroll 1
        for (int t = 0; t < TPC; ++t) {
            const int b = t & 1;
            BAR_SYNC(1 + b);                           // full[b]: P/V ready
            const uint32_t pb = smb + SM_P + b * PB;
            const uint32_t vb = smb + SM_V + b * VB;
            #pragma unroll
            for (int k = 0; k < 4; ++k) {
                uint32_t afr[2][4], bfr[4][2];
                uint32_t aaddr = pb + (uint32_t)((wm * 32 + (lane & 15)) * (PSTR_P * 2)
                                         + (k * 16 + (lane >> 4) * 8) * 2);
                ldsm_x4(aaddr,                     afr[0][0], afr[0][1], afr[0][2], afr[0][3]);
                ldsm_x4(aaddr + 16 * (PSTR_P * 2), afr[1][0], afr[1][1], afr[1][2], afr[1][3]);

                uint32_t baddr = vb + (uint32_t)((k * 16 + (lane & 15)) * (PSTR_V * 2)
                                         + (wn * 32 + (lane >> 4) * 8) * 2);
                ldsm_x4_t(baddr,      bfr[0][0], bfr[0][1], bfr[1][0], bfr[1][1]);
                ldsm_x4_t(baddr + 32, bfr[2][0], bfr[2][1], bfr[3][0], bfr[3][1]);

                #pragma unroll
                for (int mt = 0; mt < 2; ++mt)
                    #pragma unroll
                    for (int nt = 0; nt < 4; ++nt)
                        mma16816(acc[mt][nt], afr[mt], bfr[nt]);
            }
            BAR_ARRIVE(3 + b);                         // empty[b]
        }

        __syncthreads();                               // producers done -> rs final

        float* pc = g_pc + ((size_t)s * NIT + it) * (TILE_M * 128);
        #pragma unroll
        for (int mt = 0; mt < 2; ++mt) {
            int rlo = wm * 32 + mt * 16 + (lane >> 2);
            int rhi = rlo + 8;
            #pragma unroll
            for (int nt = 0; nt < 4; ++nt) {
                int col = wn * 32 + nt * 8 + 2 * (lane & 3);
                *(float2*)(pc + (size_t)rlo * 128 + col) = make_float2(acc[mt][nt][0], acc[mt][nt][1]);
                *(float2*)(pc + (size_t)rhi * 128 + col) = make_float2(acc[mt][nt][2], acc[mt][nt][3]);
            }
        }
        if (tid < TILE_M) g_prs[(size_t)s * N_TOK + i0 + tid] = rs[tid];
        return;
    }
    __syncthreads();   // producer side of the final barrier
}

// ---------------- combine ----------------
__global__ __launch_bounds__(256) void combine_kernel(float* __restrict__ out) {
    int gw   = (blockIdx.x * blockDim.x + threadIdx.x) >> 5;
    int lane = threadIdx.x & 31;
    if (gw >= N_TOK) return;

    const size_t roff = (size_t)gw * 128 + lane * 4;
    float4 c0 = *(const float4*)(g_pc + roff);
    float4 c1 = *(const float4*)(g_pc + (size_t)N_TOK * 128 + roff);
    float4 c2 = *(const float4*)(g_pc + (size_t)2 * N_TOK * 128 + roff);
    float rsum = g_prs[gw] + g_prs[N_TOK + gw] + g_prs[2 * N_TOK + gw];
    float inv = 1.f / rsum;

    float4 y;
    y.x = (c0.x + c1.x + c2.x) * inv;
    y.y = (c0.y + c1.y + c2.y) * inv;
    y.z = (c0.z + c1.z + c2.z) * inv;
    y.w = (c0.w + c1.w + c2.w) * inv;

    float ss = y.x * y.x + y.y * y.y + y.z * y.z + y.w * y.w;
    #pragma unroll
    for (int o = 16; o; o >>= 1) ss += __shfl_xor_sync(0xffffffffu, ss, o);

    float nn = fmaxf(sqrtf(ss), 1e-7f);
    float t  = tanhf(nn);
    float f  = ((t > 0.999f) ? 0.999f : t) / nn;

    y.x *= f; y.y *= f; y.z *= f; y.w *= f;
    *(float4*)(out + roff) = y;
}

// ---------------- launch ----------------
extern "C" void kernel_launch(void* const* d_in, const int* in_sizes, int n_in,
                              void* d_out, int out_size) {
    const float* x   = (const float*)d_in[0];
    const int*   adj = (const int*)d_in[1];
    const float* a   = (const float*)d_in[2];
    float*       out = (float*)d_out;

    cudaFuncSetAttribute(attn_kernel, cudaFuncAttributeMaxDynamicSharedMemorySize, SMEM_TOTAL);

    prep_kernel<<<N_TOK / 8, 256>>>(x, a);
    attn_kernel<<<NSPLIT * NIT, NTHREADS, SMEM_TOTAL>>>(adj);
    combine_kernel<<<N_TOK / 8, 256>>>(out);
}

// round 16
// speedup vs baseline: 1.3610x; 1.3610x over previous
#include <cuda_runtime.h>
#include <cuda_fp16.h>
#include <cstdint>

#define N_TOK  12288
#define TILE_M 128
#define TILE_N 64
#define NIT    96          // i-tiles
#define NSPLIT 3
#define TPC    64          // j-tiles per CTA
#define PSCALE 0.7f

// smem byte offsets (swizzled, unpadded layouts)
#define SM_P    0          // 2 x 16384 (P: 128 rows x 128 B)
#define SM_V    32768      // 2 x 16384 (V: 64 rows x 256 B)
#define SM_ADJ  65536      // 1 x 32768 (adj: tid*16 + q*8192, self-owned)
#define SM_RS   98304      // 128 floats
#define SMEM_TOTAL 98816

// ---------------- scratch (static device globals) ----------------
__device__ __half g_xt[(size_t)N_TOK * 128];
__device__ float  g_e1[N_TOK];
__device__ float  g_e1p[N_TOK];
__device__ float  g_e2[N_TOK];
__device__ float  g_e2p[N_TOK];
__device__ float  g_pc[(size_t)NSPLIT * N_TOK * 128];   // partial C
__device__ float  g_prs[(size_t)NSPLIT * N_TOK];        // partial rowsums

// ---------------- PTX helpers ----------------
__device__ __forceinline__ uint32_t smem_u32(const void* p) {
    return (uint32_t)__cvta_generic_to_shared(p);
}
__device__ __forceinline__ void cp16(uint32_t dst, const void* src) {
    asm volatile("cp.async.cg.shared.global [%0], [%1], 16;" :: "r"(dst), "l"(src));
}
#define CP_COMMIT() asm volatile("cp.async.commit_group;" ::: "memory")
#define CP_WAIT(n)  asm volatile("cp.async.wait_group %0;" :: "n"(n) : "memory")
__device__ __forceinline__ void ldsm_x4(uint32_t addr, uint32_t& r0, uint32_t& r1,
                                        uint32_t& r2, uint32_t& r3) {
    asm volatile("ldmatrix.sync.aligned.m8n8.x4.shared.b16 {%0,%1,%2,%3}, [%4];"
                 : "=r"(r0), "=r"(r1), "=r"(r2), "=r"(r3) : "r"(addr));
}
__device__ __forceinline__ void ldsm_x4_t(uint32_t addr, uint32_t& r0, uint32_t& r1,
                                          uint32_t& r2, uint32_t& r3) {
    asm volatile("ldmatrix.sync.aligned.m8n8.x4.trans.shared.b16 {%0,%1,%2,%3}, [%4];"
                 : "=r"(r0), "=r"(r1), "=r"(r2), "=r"(r3) : "r"(addr));
}
__device__ __forceinline__ void mma16816(float* c, const uint32_t* a, const uint32_t* b) {
    asm volatile("mma.sync.aligned.m16n8k16.row.col.f32.f16.f16.f32 "
                 "{%0,%1,%2,%3}, {%4,%5,%6,%7}, {%8,%9}, {%0,%1,%2,%3};"
                 : "+f"(c[0]), "+f"(c[1]), "+f"(c[2]), "+f"(c[3])
                 : "r"(a[0]), "r"(a[1]), "r"(a[2]), "r"(a[3]), "r"(b[0]), "r"(b[1]));
}

// ---------------- prep ----------------
__global__ __launch_bounds__(256) void prep_kernel(const float* __restrict__ x,
                                                   const float* __restrict__ a) {
    int gw   = (blockIdx.x * blockDim.x + threadIdx.x) >> 5;
    int lane = threadIdx.x & 31;
    if (gw >= N_TOK) return;

    const float4 xv = ((const float4*)(x + (size_t)gw * 128))[lane];
    float ss = xv.x * xv.x + xv.y * xv.y + xv.z * xv.z + xv.w * xv.w;
    #pragma unroll
    for (int o = 16; o; o >>= 1) ss += __shfl_xor_sync(0xffffffffu, ss, o);

    float norm = sqrtf(ss);
    float n    = fminf(fmaxf(norm, 1e-7f), 1.0f - 1e-7f);
    float fac  = atanhf(n) / n;
    float t0 = xv.x * fac, t1 = xv.y * fac, t2 = xv.z * fac, t3 = xv.w * fac;

    const float4 a1 = ((const float4*)a)[lane];
    const float4 a2 = ((const float4*)(a + 128))[lane];
    float w1 = t0 * a1.x + t1 * a1.y + t2 * a1.z + t3 * a1.w;
    float w2 = t0 * a2.x + t1 * a2.y + t2 * a2.z + t3 * a2.w;
    #pragma unroll
    for (int o = 16; o; o >>= 1) {
        w1 += __shfl_xor_sync(0xffffffffu, w1, o);
        w2 += __shfl_xor_sync(0xffffffffu, w2, o);
    }

    __half2* dst = (__half2*)(g_xt + (size_t)gw * 128);
    dst[lane * 2]     = __floats2half2_rn(t0, t1);
    dst[lane * 2 + 1] = __floats2half2_rn(t2, t3);

    if (lane == 0) {
        g_e1 [gw] = PSCALE * __expf(w1);
        g_e1p[gw] = PSCALE * __expf(0.2f * w1);
        g_e2 [gw] = __expf(w2);
        g_e2p[gw] = __expf(0.2f * w2);
    }
}

// ---------------- attention partial ----------------
__global__ __launch_bounds__(512, 2) void attn_kernel(const int* __restrict__ adj) {
    extern __shared__ char smem[];
    float* rs = (float*)(smem + SM_RS);

    const int tid = threadIdx.x;
    const int s   = blockIdx.x / NIT;
    const int it  = blockIdx.x % NIT;
    const int i0  = it * TILE_M;
    const int jtb = s * TPC;

    const int il = tid >> 2, jq = tid & 3;    // pgen: row il, 16-col slice jq
    const int lane = tid & 31, wid = tid >> 5;
    const int wm = wid & 3, wn = wid >> 2;

    if (tid < TILE_M) rs[tid] = 0.f;
    __syncthreads();

    float acc[2][4][4];
    #pragma unroll
    for (int mt = 0; mt < 2; ++mt)
        #pragma unroll
        for (int nt = 0; nt < 4; ++nt)
            #pragma unroll
            for (int e = 0; e < 4; ++e) acc[mt][nt][e] = 0.f;

    const float e1  = g_e1 [i0 + il];
    const float e1p = g_e1p[i0 + il];
    const int* agbase = adj + (size_t)(i0 + il) * N_TOK + jq * 16;
    const uint32_t smb = smem_u32(smem);

    auto adj_cp = [&](int jt) {               // self-owned 64 B slice
        const int* src = agbase + jt * TILE_N;
        uint32_t dst = smb + SM_ADJ + tid * 16;
        #pragma unroll
        for (int q = 0; q < 4; ++q) cp16(dst + q * 8192, src + q * 4);
    };
    auto v_cp = [&](int jt, int b) {          // V tile 64 x 128 fp16, swizzled
        const __half* src = g_xt + (size_t)jt * TILE_N * 128;
        #pragma unroll
        for (int q = 0; q < 2; ++q) {
            int idx = q * 512 + tid;
            int r = idx >> 4, ch = idx & 15;
            cp16(smb + SM_V + b * 16384 + r * 256 + ((ch ^ (r & 7)) * 16),
                 src + (size_t)r * 128 + ch * 8);
        }
    };
    auto pgen = [&](int jt, int b) {
        const int j0 = jt * TILE_N;
        const float4* e2v  = (const float4*)(g_e2  + j0 + jq * 16);
        const float4* e2pv = (const float4*)(g_e2p + j0 + jq * 16);
        union { __half h[16]; uint4 u4[2]; } pk;
        float psum = 0.f;
        #pragma unroll
        for (int q = 0; q < 4; ++q) {
            uint4 av = *(const uint4*)(smem + SM_ADJ + q * 8192 + tid * 16);
            float4 ev  = __ldg(e2v + q);
            float4 epv = __ldg(e2pv + q);
            float p0 = fmaxf(e1 * ev.x, e1p * epv.x);
            float p1 = fmaxf(e1 * ev.y, e1p * epv.y);
            float p2 = fmaxf(e1 * ev.z, e1p * epv.z);
            float p3 = fmaxf(e1 * ev.w, e1p * epv.w);
            p0 = av.x ? p0 : 0.f;  p1 = av.y ? p1 : 0.f;
            p2 = av.z ? p2 : 0.f;  p3 = av.w ? p3 : 0.f;
            psum += (p0 + p1) + (p2 + p3);
            pk.h[q * 4 + 0] = __float2half_rn(p0);
            pk.h[q * 4 + 1] = __float2half_rn(p1);
            pk.h[q * 4 + 2] = __float2half_rn(p2);
            pk.h[q * 4 + 3] = __float2half_rn(p3);
        }
        // P row il (128 B), chunks jq*2, jq*2+1, XOR-swizzled
        #pragma unroll
        for (int q = 0; q < 2; ++q) {
            int ch = jq * 2 + q;
            *(uint4*)(smem + SM_P + b * 16384 + il * 128 + ((ch ^ (il & 7)) * 16)) = pk.u4[q];
        }
        psum += __shfl_xor_sync(0xffffffffu, psum, 1);
        psum += __shfl_xor_sync(0xffffffffu, psum, 2);
        if (jq == 0) rs[il] += psum;
    };
    auto mma_tile = [&](int b) {
        const uint32_t pb = smb + SM_P + b * 16384;
        const uint32_t vb = smb + SM_V + b * 16384;
        #pragma unroll
        for (int k = 0; k < 4; ++k) {
            uint32_t afr[2][4], bfr[4][2];
            {   // P rows wm*32+(lane&15) (+16), chunk k*2+(lane>>4), swizzled
                int r0 = wm * 32 + (lane & 15);
                int ch = k * 2 + (lane >> 4);
                uint32_t a0 = pb + (uint32_t)(r0 * 128 + ((ch ^ (r0 & 7)) * 16));
                int r1 = r0 + 16;
                uint32_t a1 = pb + (uint32_t)(r1 * 128 + ((ch ^ (r1 & 7)) * 16));
                ldsm_x4(a0, afr[0][0], afr[0][1], afr[0][2], afr[0][3]);
                ldsm_x4(a1, afr[1][0], afr[1][1], afr[1][2], afr[1][3]);
            }
            {   // V rows k*16+(lane&15), chunk wn*4+(lane>>4) (+2), swizzled
                int r = k * 16 + (lane & 15);
                int ch0 = wn * 4 + (lane >> 4);
                uint32_t b0 = vb + (uint32_t)(r * 256 + ((ch0 ^ (r & 7)) * 16));
                int ch1 = ch0 + 2;
                uint32_t b1 = vb + (uint32_t)(r * 256 + ((ch1 ^ (r & 7)) * 16));
                ldsm_x4_t(b0, bfr[0][0], bfr[0][1], bfr[1][0], bfr[1][1]);
                ldsm_x4_t(b1, bfr[2][0], bfr[2][1], bfr[3][0], bfr[3][1]);
            }
            #pragma unroll
            for (int mt = 0; mt < 2; ++mt)
                #pragma unroll
                for (int nt = 0; nt < 4; ++nt)
                    mma16816(acc[mt][nt], afr[mt], bfr[nt]);
        }
    };

    // ---- prologue ----
    adj_cp(jtb);      CP_COMMIT();            // A0
    v_cp(jtb, 0);     CP_COMMIT();            // V0
    CP_WAIT(1);                               // A0 done
    pgen(jtb, 0);
    adj_cp(jtb + 1);  CP_COMMIT();            // A1 (own slice consumed already)
    CP_WAIT(1);                               // V0 done (A1 may fly)

    // ---- main loop: one sync per iteration ----
    #pragma unroll 1
    for (int t = 0; t < TPC; ++t) {
        __syncthreads();                      // publish P/V(t); MMA(t-1) done
        const bool more = (t + 1 < TPC);
        if (more) { v_cp(jtb + t + 1, (t + 1) & 1); CP_COMMIT(); }   // V(t+1)
        mma_tile(t & 1);                      // hides adj(t+1) + V(t+1) latency
        if (more) {
            CP_WAIT(1);                       // A(t+1) done (V(t+1) may fly)
            pgen(jtb + t + 1, (t + 1) & 1);
            if (t + 2 < TPC) { adj_cp(jtb + t + 2); CP_COMMIT(); CP_WAIT(1); }
            else             { CP_WAIT(0); }  // V(t+1) done
        }
    }

    // ---- write partials ----
    __syncthreads();                          // rs final
    float* pc = g_pc + ((size_t)s * NIT + it) * (TILE_M * 128);
    #pragma unroll
    for (int mt = 0; mt < 2; ++mt) {
        int rlo = wm * 32 + mt * 16 + (lane >> 2);
        int rhi = rlo + 8;
        #pragma unroll
        for (int nt = 0; nt < 4; ++nt) {
            int col = wn * 32 + nt * 8 + 2 * (lane & 3);
            *(float2*)(pc + (size_t)rlo * 128 + col) = make_float2(acc[mt][nt][0], acc[mt][nt][1]);
            *(float2*)(pc + (size_t)rhi * 128 + col) = make_float2(acc[mt][nt][2], acc[mt][nt][3]);
        }
    }
    if (tid < TILE_M) g_prs[(size_t)s * N_TOK + i0 + tid] = rs[tid];
}

// ---------------- combine ----------------
__global__ __launch_bounds__(256) void combine_kernel(float* __restrict__ out) {
    int gw   = (blockIdx.x * blockDim.x + threadIdx.x) >> 5;
    int lane = threadIdx.x & 31;
    if (gw >= N_TOK) return;

    const size_t roff = (size_t)gw * 128 + lane * 4;
    float4 c0 = *(const float4*)(g_pc + roff);
    float4 c1 = *(const float4*)(g_pc + (size_t)N_TOK * 128 + roff);
    float4 c2 = *(const float4*)(g_pc + (size_t)2 * N_TOK * 128 + roff);
    float rsum = g_prs[gw] + g_prs[N_TOK + gw] + g_prs[2 * N_TOK + gw];
    float inv = 1.f / rsum;

    float4 y;
    y.x = (c0.x + c1.x + c2.x) * inv;
    y.y = (c0.y + c1.y + c2.y) * inv;
    y.z = (c0.z + c1.z + c2.z) * inv;
    y.w = (c0.w + c1.w + c2.w) * inv;

    float ss = y.x * y.x + y.y * y.y + y.z * y.z + y.w * y.w;
    #pragma unroll
    for (int o = 16; o; o >>= 1) ss += __shfl_xor_sync(0xffffffffu, ss, o);

    float nn = fmaxf(sqrtf(ss), 1e-7f);
    float t  = tanhf(nn);
    float f  = ((t > 0.999f) ? 0.999f : t) / nn;

    y.x *= f; y.y *= f; y.z *= f; y.w *= f;
    *(float4*)(out + roff) = y;
}

// ---------------- launch ----------------
extern "C" void kernel_launch(void* const* d_in, const int* in_sizes, int n_in,
                              void* d_out, int out_size) {
    const float* x   = (const float*)d_in[0];
    const int*   adj = (const int*)d_in[1];
    const float* a   = (const float*)d_in[2];
    float*       out = (float*)d_out;

    cudaFuncSetAttribute(attn_kernel, cudaFuncAttributeMaxDynamicSharedMemorySize, SMEM_TOTAL);

    prep_kernel<<<N_TOK / 8, 256>>>(x, a);
    attn_kernel<<<NSPLIT * NIT, 512, SMEM_TOTAL>>>(adj);
    combine_kernel<<<N_TOK / 8, 256>>>(out);
}